// round 1
// baseline (speedup 1.0000x reference)
#include <cuda_runtime.h>

#define N_NODES 50000
#define N_EDGES 800000
#define N_GRAPHS 32
#define D 128
#define H 256

// ---------------- scratch (device globals: allocation-free kernel_launch) ----
__device__ float g_x[N_NODES * D];
__device__ float g_agg[N_NODES * D];
__device__ float g_d2[N_EDGES];

__device__ __forceinline__ float swishf(float v) {
    return v / (1.f + __expf(-v));
}

// ---------------- small utility kernels --------------------------------------
__global__ void zero_agg_kernel() {
    int i = blockIdx.x * blockDim.x + threadIdx.x;
    if (i < N_NODES * D) g_agg[i] = 0.f;
}

__global__ void zero_out_kernel(float* __restrict__ out) {
    if (threadIdx.x < N_GRAPHS) out[threadIdx.x] = 0.f;
}

__global__ void d2_kernel(const float* __restrict__ pos,
                          const float* __restrict__ shift,
                          const float* __restrict__ lat,
                          const int* __restrict__ ei,
                          const int* __restrict__ batch) {
    int e = blockIdx.x * blockDim.x + threadIdx.x;
    if (e >= N_EDGES) return;
    int s = ei[e];
    int d = ei[N_EDGES + e];
    int g = batch[s];
    const float* L = lat + g * 9;
    float sx = shift[e * 3 + 0], sy = shift[e * 3 + 1], sz = shift[e * 3 + 2];
    float vx = pos[d * 3 + 0] - pos[s * 3 + 0] + sx * L[0] + sy * L[3] + sz * L[6];
    float vy = pos[d * 3 + 1] - pos[s * 3 + 1] + sx * L[1] + sy * L[4] + sz * L[7];
    float vz = pos[d * 3 + 2] - pos[s * 3 + 2] + sx * L[2] + sy * L[5] + sz * L[8];
    g_d2[e] = vx * vx + vy * vy + vz * vz;
}

__global__ void embed_kernel(const float* __restrict__ embed,
                             const int* __restrict__ z) {
    int i = blockIdx.x * blockDim.x + threadIdx.x;
    if (i >= N_NODES * D) return;
    int n = i >> 7, c = i & 127;
    g_x[i] = embed[z[n] * D + c];
}

// ---------------- fused edge MLP + scatter-add --------------------------------
// block = 32 edges, 256 threads.
// GEMM1: m1[32,256] = swish(ein[32,257] @ W1 + b1)   (ein = [x[dst] | x[src] | d2])
// GEMM2: m2[32,128] = swish(m1 @ W2 + b2)            then atomicAdd into agg[dst].
// Thread tile GEMM1: 4 edges x 8 cols (cols {cg*4..+3, 128+cg*4..+3} -> conflict-free LDS.128)
// Thread tile GEMM2: 4 edges x 4 cols.
__global__ __launch_bounds__(256) void edge_kernel(
    const float* __restrict__ W1, const float* __restrict__ b1,
    const float* __restrict__ W2, const float* __restrict__ b2,
    const int* __restrict__ ei)
{
    extern __shared__ float sm[];
    float* s_in = sm;                       // [32][256]
    float* s_w  = sm + 8192;                // weight staging [32][256]
    float* s_d2 = sm + 16384;               // [32]
    int*   s_src = (int*)(sm + 16384 + 32); // [32]
    int*   s_dst = s_src + 32;              // [32]

    const int t  = threadIdx.x;
    const int e0 = blockIdx.x * 32;
    if (t < 32) {
        s_src[t] = ei[e0 + t];
        s_dst[t] = ei[N_EDGES + e0 + t];
        s_d2[t]  = g_d2[e0 + t];
    }
    __syncthreads();

    // gather ein: cols 0..127 = x[dst], 128..255 = x[src]
    #pragma unroll
    for (int i = t; i < 32 * 64; i += 256) {
        const int e = i >> 6, q = i & 63;
        const float4* p = (q < 32)
            ? ((const float4*)(g_x + (size_t)s_dst[e] * D) + q)
            : ((const float4*)(g_x + (size_t)s_src[e] * D) + (q - 32));
        ((float4*)(s_in + e * 256))[q] = *p;
    }

    const int eg = t >> 5;   // edge group 0..7 -> edges eg*4..+3
    const int cg = t & 31;   // col group   0..31

    float acc[4][8];
    #pragma unroll
    for (int i = 0; i < 4; i++)
        #pragma unroll
        for (int j = 0; j < 8; j++) acc[i][j] = 0.f;

    // ---- GEMM1 over K=256 (rows 0..255 of W1); d2 row (256) folded in epilogue
    for (int k0 = 0; k0 < 256; k0 += 32) {
        __syncthreads();
        #pragma unroll
        for (int i = t; i < 2048; i += 256)
            ((float4*)s_w)[i] = ((const float4*)W1)[k0 * 64 + i];
        __syncthreads();
        #pragma unroll
        for (int kk4 = 0; kk4 < 32; kk4 += 4) {
            float xs[4][4];
            #pragma unroll
            for (int i = 0; i < 4; i++) {
                float4 xv = *((const float4*)(s_in + (eg * 4 + i) * 256 + k0 + kk4));
                xs[i][0] = xv.x; xs[i][1] = xv.y; xs[i][2] = xv.z; xs[i][3] = xv.w;
            }
            #pragma unroll
            for (int u = 0; u < 4; u++) {
                const int kk = kk4 + u;
                float4 w0 = *((const float4*)(s_w + kk * 256 + cg * 4));
                float4 w1 = *((const float4*)(s_w + kk * 256 + 128 + cg * 4));
                #pragma unroll
                for (int i = 0; i < 4; i++) {
                    float xv = xs[i][u];
                    acc[i][0] = fmaf(xv, w0.x, acc[i][0]);
                    acc[i][1] = fmaf(xv, w0.y, acc[i][1]);
                    acc[i][2] = fmaf(xv, w0.z, acc[i][2]);
                    acc[i][3] = fmaf(xv, w0.w, acc[i][3]);
                    acc[i][4] = fmaf(xv, w1.x, acc[i][4]);
                    acc[i][5] = fmaf(xv, w1.y, acc[i][5]);
                    acc[i][6] = fmaf(xv, w1.z, acc[i][6]);
                    acc[i][7] = fmaf(xv, w1.w, acc[i][7]);
                }
            }
        }
    }

    // epilogue: + d2 * W1[256,:] + b1, swish, store m1 back into s_in
    float4 wd0 = *((const float4*)(W1 + 256 * 256 + cg * 4));
    float4 wd1 = *((const float4*)(W1 + 256 * 256 + 128 + cg * 4));
    float4 bb0 = *((const float4*)(b1 + cg * 4));
    float4 bb1 = *((const float4*)(b1 + 128 + cg * 4));

    __syncthreads();
    #pragma unroll
    for (int i = 0; i < 4; i++) {
        float dv = s_d2[eg * 4 + i];
        float4 r0, r1;
        r0.x = swishf(fmaf(dv, wd0.x, acc[i][0]) + bb0.x);
        r0.y = swishf(fmaf(dv, wd0.y, acc[i][1]) + bb0.y);
        r0.z = swishf(fmaf(dv, wd0.z, acc[i][2]) + bb0.z);
        r0.w = swishf(fmaf(dv, wd0.w, acc[i][3]) + bb0.w);
        r1.x = swishf(fmaf(dv, wd1.x, acc[i][4]) + bb1.x);
        r1.y = swishf(fmaf(dv, wd1.y, acc[i][5]) + bb1.y);
        r1.z = swishf(fmaf(dv, wd1.z, acc[i][6]) + bb1.z);
        r1.w = swishf(fmaf(dv, wd1.w, acc[i][7]) + bb1.w);
        *((float4*)(s_in + (eg * 4 + i) * 256 + cg * 4)) = r0;
        *((float4*)(s_in + (eg * 4 + i) * 256 + 128 + cg * 4)) = r1;
    }

    // ---- GEMM2: [32,256] @ [256,128]
    float a2[4][4];
    #pragma unroll
    for (int i = 0; i < 4; i++)
        #pragma unroll
        for (int j = 0; j < 4; j++) a2[i][j] = 0.f;

    for (int k0 = 0; k0 < 256; k0 += 32) {
        __syncthreads();
        #pragma unroll
        for (int i = t; i < 1024; i += 256)
            ((float4*)s_w)[i] = ((const float4*)W2)[k0 * 32 + i];
        __syncthreads();
        #pragma unroll
        for (int kk4 = 0; kk4 < 32; kk4 += 4) {
            float xs[4][4];
            #pragma unroll
            for (int i = 0; i < 4; i++) {
                float4 xv = *((const float4*)(s_in + (eg * 4 + i) * 256 + k0 + kk4));
                xs[i][0] = xv.x; xs[i][1] = xv.y; xs[i][2] = xv.z; xs[i][3] = xv.w;
            }
            #pragma unroll
            for (int u = 0; u < 4; u++) {
                const int kk = kk4 + u;
                float4 wv = *((const float4*)(s_w + kk * 128 + cg * 4));
                #pragma unroll
                for (int i = 0; i < 4; i++) {
                    float xv = xs[i][u];
                    a2[i][0] = fmaf(xv, wv.x, a2[i][0]);
                    a2[i][1] = fmaf(xv, wv.y, a2[i][1]);
                    a2[i][2] = fmaf(xv, wv.z, a2[i][2]);
                    a2[i][3] = fmaf(xv, wv.w, a2[i][3]);
                }
            }
        }
    }

    float4 bb = *((const float4*)(b2 + cg * 4));
    #pragma unroll
    for (int i = 0; i < 4; i++) {
        float* ap = g_agg + (size_t)s_dst[eg * 4 + i] * D + cg * 4;
        atomicAdd(ap + 0, swishf(a2[i][0] + bb.x));
        atomicAdd(ap + 1, swishf(a2[i][1] + bb.y));
        atomicAdd(ap + 2, swishf(a2[i][2] + bb.z));
        atomicAdd(ap + 3, swishf(a2[i][3] + bb.w));
    }
}

// ---------------- fused node MLP (residual) -----------------------------------
__global__ __launch_bounds__(256) void node_kernel(
    const float* __restrict__ W1, const float* __restrict__ b1,
    const float* __restrict__ W2, const float* __restrict__ b2)
{
    extern __shared__ float sm[];
    float* s_in = sm;        // [32][256]
    float* s_w  = sm + 8192; // staging

    const int t  = threadIdx.x;
    const int n0 = blockIdx.x * 32;

    // gather hin = [x[n] | agg[n]]
    #pragma unroll
    for (int i = t; i < 32 * 64; i += 256) {
        const int r = i >> 6, q = i & 63;
        int n = n0 + r; if (n >= N_NODES) n = N_NODES - 1;
        ((float4*)(s_in + r * 256))[q] = (q < 32)
            ? ((const float4*)(g_x + (size_t)n * D))[q]
            : ((const float4*)(g_agg + (size_t)n * D))[q - 32];
    }

    const int eg = t >> 5;
    const int cg = t & 31;

    float acc[4][8];
    #pragma unroll
    for (int i = 0; i < 4; i++)
        #pragma unroll
        for (int j = 0; j < 8; j++) acc[i][j] = 0.f;

    for (int k0 = 0; k0 < 256; k0 += 32) {
        __syncthreads();
        #pragma unroll
        for (int i = t; i < 2048; i += 256)
            ((float4*)s_w)[i] = ((const float4*)W1)[k0 * 64 + i];
        __syncthreads();
        #pragma unroll
        for (int kk4 = 0; kk4 < 32; kk4 += 4) {
            float xs[4][4];
            #pragma unroll
            for (int i = 0; i < 4; i++) {
                float4 xv = *((const float4*)(s_in + (eg * 4 + i) * 256 + k0 + kk4));
                xs[i][0] = xv.x; xs[i][1] = xv.y; xs[i][2] = xv.z; xs[i][3] = xv.w;
            }
            #pragma unroll
            for (int u = 0; u < 4; u++) {
                const int kk = kk4 + u;
                float4 w0 = *((const float4*)(s_w + kk * 256 + cg * 4));
                float4 w1 = *((const float4*)(s_w + kk * 256 + 128 + cg * 4));
                #pragma unroll
                for (int i = 0; i < 4; i++) {
                    float xv = xs[i][u];
                    acc[i][0] = fmaf(xv, w0.x, acc[i][0]);
                    acc[i][1] = fmaf(xv, w0.y, acc[i][1]);
                    acc[i][2] = fmaf(xv, w0.z, acc[i][2]);
                    acc[i][3] = fmaf(xv, w0.w, acc[i][3]);
                    acc[i][4] = fmaf(xv, w1.x, acc[i][4]);
                    acc[i][5] = fmaf(xv, w1.y, acc[i][5]);
                    acc[i][6] = fmaf(xv, w1.z, acc[i][6]);
                    acc[i][7] = fmaf(xv, w1.w, acc[i][7]);
                }
            }
        }
    }

    float4 bb0 = *((const float4*)(b1 + cg * 4));
    float4 bb1 = *((const float4*)(b1 + 128 + cg * 4));

    __syncthreads();
    #pragma unroll
    for (int i = 0; i < 4; i++) {
        float4 r0, r1;
        r0.x = swishf(acc[i][0] + bb0.x);
        r0.y = swishf(acc[i][1] + bb0.y);
        r0.z = swishf(acc[i][2] + bb0.z);
        r0.w = swishf(acc[i][3] + bb0.w);
        r1.x = swishf(acc[i][4] + bb1.x);
        r1.y = swishf(acc[i][5] + bb1.y);
        r1.z = swishf(acc[i][6] + bb1.z);
        r1.w = swishf(acc[i][7] + bb1.w);
        *((float4*)(s_in + (eg * 4 + i) * 256 + cg * 4)) = r0;
        *((float4*)(s_in + (eg * 4 + i) * 256 + 128 + cg * 4)) = r1;
    }

    float a2[4][4];
    #pragma unroll
    for (int i = 0; i < 4; i++)
        #pragma unroll
        for (int j = 0; j < 4; j++) a2[i][j] = 0.f;

    for (int k0 = 0; k0 < 256; k0 += 32) {
        __syncthreads();
        #pragma unroll
        for (int i = t; i < 1024; i += 256)
            ((float4*)s_w)[i] = ((const float4*)W2)[k0 * 32 + i];
        __syncthreads();
        #pragma unroll
        for (int kk4 = 0; kk4 < 32; kk4 += 4) {
            float xs[4][4];
            #pragma unroll
            for (int i = 0; i < 4; i++) {
                float4 xv = *((const float4*)(s_in + (eg * 4 + i) * 256 + k0 + kk4));
                xs[i][0] = xv.x; xs[i][1] = xv.y; xs[i][2] = xv.z; xs[i][3] = xv.w;
            }
            #pragma unroll
            for (int u = 0; u < 4; u++) {
                const int kk = kk4 + u;
                float4 wv = *((const float4*)(s_w + kk * 128 + cg * 4));
                #pragma unroll
                for (int i = 0; i < 4; i++) {
                    float xv = xs[i][u];
                    a2[i][0] = fmaf(xv, wv.x, a2[i][0]);
                    a2[i][1] = fmaf(xv, wv.y, a2[i][1]);
                    a2[i][2] = fmaf(xv, wv.z, a2[i][2]);
                    a2[i][3] = fmaf(xv, wv.w, a2[i][3]);
                }
            }
        }
    }

    float4 bb = *((const float4*)(b2 + cg * 4));
    #pragma unroll
    for (int i = 0; i < 4; i++) {
        int n = n0 + eg * 4 + i;
        if (n < N_NODES) {
            float4* xp = (float4*)(g_x + (size_t)n * D + cg * 4);
            float4 o = *xp;
            o.x += a2[i][0] + bb.x;
            o.y += a2[i][1] + bb.y;
            o.z += a2[i][2] + bb.z;
            o.w += a2[i][3] + bb.w;
            *xp = o;
        }
    }
}

// ---------------- output head + graph pooling ---------------------------------
__global__ __launch_bounds__(256) void out_kernel(
    const float* __restrict__ W1, const float* __restrict__ b1,
    const float* __restrict__ w2, const float* __restrict__ b2,
    const int* __restrict__ batch, float* __restrict__ out)
{
    extern __shared__ float sm[];
    float* s_in = sm;        // [32][128]
    float* s_w  = sm + 4096; // [32][256]

    const int t  = threadIdx.x;
    const int n0 = blockIdx.x * 32;

    #pragma unroll
    for (int i = t; i < 1024; i += 256) {
        const int r = i >> 5, q = i & 31;
        int n = n0 + r; if (n >= N_NODES) n = N_NODES - 1;
        ((float4*)(s_in + r * 128))[q] = ((const float4*)(g_x + (size_t)n * D))[q];
    }

    const int eg = t >> 5;
    const int cg = t & 31;

    float acc[4][8];
    #pragma unroll
    for (int i = 0; i < 4; i++)
        #pragma unroll
        for (int j = 0; j < 8; j++) acc[i][j] = 0.f;

    for (int k0 = 0; k0 < 128; k0 += 32) {
        __syncthreads();
        #pragma unroll
        for (int i = t; i < 2048; i += 256)
            ((float4*)s_w)[i] = ((const float4*)W1)[k0 * 64 + i];
        __syncthreads();
        #pragma unroll
        for (int kk4 = 0; kk4 < 32; kk4 += 4) {
            float xs[4][4];
            #pragma unroll
            for (int i = 0; i < 4; i++) {
                float4 xv = *((const float4*)(s_in + (eg * 4 + i) * 128 + k0 + kk4));
                xs[i][0] = xv.x; xs[i][1] = xv.y; xs[i][2] = xv.z; xs[i][3] = xv.w;
            }
            #pragma unroll
            for (int u = 0; u < 4; u++) {
                const int kk = kk4 + u;
                float4 w0 = *((const float4*)(s_w + kk * 256 + cg * 4));
                float4 w1 = *((const float4*)(s_w + kk * 256 + 128 + cg * 4));
                #pragma unroll
                for (int i = 0; i < 4; i++) {
                    float xv = xs[i][u];
                    acc[i][0] = fmaf(xv, w0.x, acc[i][0]);
                    acc[i][1] = fmaf(xv, w0.y, acc[i][1]);
                    acc[i][2] = fmaf(xv, w0.z, acc[i][2]);
                    acc[i][3] = fmaf(xv, w0.w, acc[i][3]);
                    acc[i][4] = fmaf(xv, w1.x, acc[i][4]);
                    acc[i][5] = fmaf(xv, w1.y, acc[i][5]);
                    acc[i][6] = fmaf(xv, w1.z, acc[i][6]);
                    acc[i][7] = fmaf(xv, w1.w, acc[i][7]);
                }
            }
        }
    }

    float4 bb0 = *((const float4*)(b1 + cg * 4));
    float4 bb1 = *((const float4*)(b1 + 128 + cg * 4));
    float4 w2a = *((const float4*)(w2 + cg * 4));
    float4 w2b = *((const float4*)(w2 + 128 + cg * 4));

    float pv[4];
    #pragma unroll
    for (int i = 0; i < 4; i++) {
        float s = 0.f;
        s = fmaf(swishf(acc[i][0] + bb0.x), w2a.x, s);
        s = fmaf(swishf(acc[i][1] + bb0.y), w2a.y, s);
        s = fmaf(swishf(acc[i][2] + bb0.z), w2a.z, s);
        s = fmaf(swishf(acc[i][3] + bb0.w), w2a.w, s);
        s = fmaf(swishf(acc[i][4] + bb1.x), w2b.x, s);
        s = fmaf(swishf(acc[i][5] + bb1.y), w2b.y, s);
        s = fmaf(swishf(acc[i][6] + bb1.z), w2b.z, s);
        s = fmaf(swishf(acc[i][7] + bb1.w), w2b.w, s);
        pv[i] = s;
    }

    #pragma unroll
    for (int off = 16; off > 0; off >>= 1) {
        #pragma unroll
        for (int i = 0; i < 4; i++)
            pv[i] += __shfl_down_sync(0xffffffffu, pv[i], off);
    }

    if (cg == 0) {
        float bias = b2[0];
        #pragma unroll
        for (int i = 0; i < 4; i++) {
            int n = n0 + eg * 4 + i;
            if (n < N_NODES) atomicAdd(&out[batch[n]], pv[i] + bias);
        }
    }
}

// ---------------- host launcher ------------------------------------------------
extern "C" void kernel_launch(void* const* d_in, const int* in_sizes, int n_in,
                              void* d_out, int out_size) {
    const float *positions = 0, *edge_shift = 0, *lattice = 0, *embed = 0;
    const float *ew1 = 0, *eb1 = 0, *ew2 = 0, *eb2 = 0;
    const float *nw1 = 0, *nb1 = 0, *nw2 = 0, *nb2 = 0;
    const float *ow1 = 0, *ob1 = 0, *ow2 = 0, *ob2 = 0;
    const int *z = 0, *ei = 0, *batch = 0;

    // resolve inputs by element count (ambiguous sizes preserve order in both
    // plausible metadata orderings: edge_* before node_*, atomic before batch,
    // out_b1 before out_w2)
    for (int i = 0; i < n_in; i++) {
        int s = in_sizes[i];
        const void* p = d_in[i];
        switch (s) {
            case 150000:  positions  = (const float*)p; break;
            case 2400000: edge_shift = (const float*)p; break;
            case 288:     lattice    = (const float*)p; break;
            case 12800:   embed      = (const float*)p; break;
            case 197376:  ew1        = (const float*)p; break;
            case 196608:  nw1        = (const float*)p; break;
            case 32768:   ow1        = (const float*)p; break;
            case 768:     if (!eb1) eb1 = (const float*)p; else nb1 = (const float*)p; break;
            case 98304:   if (!ew2) ew2 = (const float*)p; else nw2 = (const float*)p; break;
            case 384:     if (!eb2) eb2 = (const float*)p; else nb2 = (const float*)p; break;
            case 256:     if (!ob1) ob1 = (const float*)p; else ow2 = (const float*)p; break;
            case 1:       ob2        = (const float*)p; break;
            case 1600000: ei         = (const int*)p; break;
            case 50000:   if (!z) z = (const int*)p; else batch = (const int*)p; break;
            default: break;
        }
    }

    const int EDGE_SMEM = 16384 * 4 + 32 * 4 + 64 * 4;  // 65920 B
    const int NODE_SMEM = 16384 * 4;                     // 65536 B
    const int OUT_SMEM  = (4096 + 8192) * 4;             // 49152 B
    cudaFuncSetAttribute(edge_kernel, cudaFuncAttributeMaxDynamicSharedMemorySize, EDGE_SMEM);
    cudaFuncSetAttribute(node_kernel, cudaFuncAttributeMaxDynamicSharedMemorySize, NODE_SMEM);
    cudaFuncSetAttribute(out_kernel,  cudaFuncAttributeMaxDynamicSharedMemorySize, OUT_SMEM);

    float* out = (float*)d_out;

    zero_out_kernel<<<1, 32>>>(out);
    d2_kernel<<<(N_EDGES + 255) / 256, 256>>>(positions, edge_shift, lattice, ei, batch);
    embed_kernel<<<(N_NODES * D + 255) / 256, 256>>>(embed, z);

    for (int l = 0; l < 3; l++) {
        zero_agg_kernel<<<(N_NODES * D + 255) / 256, 256>>>();
        edge_kernel<<<N_EDGES / 32, 256, EDGE_SMEM>>>(
            ew1 + (size_t)l * 257 * 256, eb1 + (size_t)l * 256,
            ew2 + (size_t)l * 256 * 128, eb2 + (size_t)l * 128, ei);
        node_kernel<<<(N_NODES + 31) / 32, 256, NODE_SMEM>>>(
            nw1 + (size_t)l * 256 * 256, nb1 + (size_t)l * 256,
            nw2 + (size_t)l * 256 * 128, nb2 + (size_t)l * 128);
    }

    out_kernel<<<(N_NODES + 31) / 32, 256, OUT_SMEM>>>(ow1, ob1, ow2, ob2, batch, out);
}